// round 13
// baseline (speedup 1.0000x reference)
#include <cuda_runtime.h>

// Problem shape (fixed by the dataset)
#define BB 256
#define SS 2048
#define HH 128
#define NB 2
#define NTHREADS 512
#define DT 0.1f
#define PAD 36            // floats per 32-float group (pad keeps STS/LDS conflict-free)
#define HPAD 144          // padded state row (4 * 36)
#define XSS (SS + 4)      // padded xe row

typedef unsigned long long ull;

// Packed fp32x2 ops (Blackwell): two fp32 lanes per instruction.
__device__ __forceinline__ ull ffma2(ull a, ull b, ull c) {
    ull d;
    asm("fma.rn.f32x2 %0, %1, %2, %3;" : "=l"(d) : "l"(a), "l"(b), "l"(c));
    return d;
}
__device__ __forceinline__ ull addf2(ull a, ull b) {
    ull d;
    asm("add.rn.f32x2 %0, %1, %2;" : "=l"(d) : "l"(a), "l"(b));
    return d;
}
__device__ __forceinline__ float fold2(ull a) {
    float lo, hi;
    asm("mov.b64 {%0, %1}, %2;" : "=f"(lo), "=f"(hi) : "l"(a));
    return lo + hi;
}
__device__ __forceinline__ float tanha(float x) {
    float t; asm("tanh.approx.f32 %0, %1;" : "=f"(t) : "f"(x)); return t;
}
__device__ __forceinline__ float shx(float v, int m) {
    return __shfl_xor_sync(0xffffffffu, v, m);
}

// Padded float offset of the i-th 16-byte chunk of a logical vector
// (32 logical floats per group of PAD). 36 floats = 144 B, 16B-aligned.
#define OFFW(i) ((((i) >> 3) * PAD) + 4 * ((i) & 7))

__global__ void __launch_bounds__(NTHREADS, 1)
liquid_scan_kernel(const float* __restrict__ x,
                   const float* __restrict__ W_in, const float* __restrict__ b_in,
                   const float* __restrict__ W_rec, const float* __restrict__ b_rec,
                   const float* __restrict__ tau,
                   const float* __restrict__ W_att, const float* __restrict__ b_att,
                   const float* __restrict__ W_ev, const float* __restrict__ b_ev,
                   const float* __restrict__ W_acc, const float* __restrict__ b_acc,
                   const float* __restrict__ W_out, const float* __restrict__ b_out,
                   float* __restrict__ out) {
    __shared__ __align__(16) float2 xe[NB][XSS];     // fused (x, ew) pairs
    __shared__ __align__(16) float hs[NB][HPAD];     // hidden state (padded)
    __shared__ __align__(16) float hatts[NB][HPAD];  // h * att (padded)

    const int tid = threadIdx.x;
    const int half = tid >> 8;       // batch: warps 0-7 -> b0, warps 8-15 -> b1
    const int u = tid & 255;
    const int row = u >> 1;          // this thread's row (0..127)
    const int part = u & 1;          // 0: att + rec-low, 1: acc + rec-high + ic
    const int b0 = blockIdx.x * NB;
    const int hoff = (row >> 5) * PAD + (row & 31);

    // ---- stage x rows into smem (.x components)
    {
        const float* xg0 = x + (size_t)b0 * SS;
        const float* xg1 = xg0 + SS;
#pragma unroll
        for (int k = 0; k < SS / NTHREADS; k++) {
            const int s = tid + k * NTHREADS;
            xe[0][s].x = xg0[s];
            xe[1][s].x = xg1[s];
        }
    }
    if (tid < NB * HPAD) ((float*)hs)[tid] = 0.0f;
    __syncthreads();

    // ---- precompute event weights into xe[.].y AND the event_weights output
    {
        const float wev0 = W_ev[0], wev1 = W_ev[1], bev = b_ev[0];
        float* out_ew = out + BB;
#pragma unroll
        for (int k = 0; k < SS / NTHREADS; k++) {
            const int s = tid + k * NTHREADS;
#pragma unroll
            for (int b = 0; b < NB; b++) {
                float e = 0.0f;
                if (s > 0) {
                    float t = tanha(0.5f * (wev0 * xe[b][s].x + wev1 * xe[b][s - 1].x + bev));
                    e = fmaf(0.5f, t, 0.5f);
                }
                xe[b][s].y = e;
                out_ew[(size_t)(b0 + b) * SS + s] = e;
            }
        }
    }

    // ---- weights: full A-matrix row (att or acc per part) + half W_rec row
    const float* WAsel = part ? W_acc : W_att;
    ulonglong2 wA[32];   // 128 floats = full row
    {
        const ulonglong2* pa = reinterpret_cast<const ulonglong2*>(WAsel + row * HH);
#pragma unroll
        for (int i = 0; i < 32; i++) wA[i] = pa[i];
    }
    ulonglong2 wR[16];   // 64 floats = this part's half of the W_rec row
    {
        const ulonglong2* pr = reinterpret_cast<const ulonglong2*>(W_rec + row * HH + 64 * part);
#pragma unroll
        for (int i = 0; i < 16; i++) wR[i] = pr[i];
    }

    const float biasA = part ? b_acc[row] : b_att[row];
    const float brec = b_rec[row];
    const float win  = W_in[row];
    const float bin  = b_in[row];
    const float itau = 1.0f / fminf(fmaxf(tau[row], 0.1f), 10.0f);

    const float* hsb = &hs[half][0];
    const float* hbp = &hatts[half][0] + part * (2 * PAD);  // part1 starts at col 64

    float hprev = 0.0f;  // h[half][row] carried in a register
    float accq = 0.0f;   // acc state (valid on part1)
    float ewpq = 0.0f;   // previous step's event weight

    __syncthreads();

#pragma unroll 1
    for (int s = 0; s < SS; s++) {
        const float2 xv = xe[half][s];   // (x_t, ew_t), warp-uniform broadcast

        // ---- phase A: one full 128-col dot per thread (att on part0, acc on part1)
        ull a0 = 0, a1 = 0;
#pragma unroll
        for (int i = 0; i < 32; i++) {
            const ulonglong2 hv = *reinterpret_cast<const ulonglong2*>(hsb + OFFW(i));
            a0 = ffma2(wA[i].x, hv.x, a0);
            a1 = ffma2(wA[i].y, hv.y, a1);
        }
        const float dA = fold2(addf2(a0, a1));
        const float inA = dA + biasA;
        const float tA = tanha(part ? inA : 0.5f * inA);
        const float vA = part ? tA : fmaf(0.5f, tA, 0.5f);
        if (!part) hatts[half][hoff] = hprev * vA;   // att gate applied
        accq = 0.9f * accq + 0.1f * vA * ewpq;       // meaningful on part1
        __syncthreads();

        // ---- phase B: half-row rec dot per thread, xor1 pair completes it
        ull r0 = 0, r1 = 0;
#pragma unroll
        for (int i = 0; i < 16; i++) {
            const ulonglong2 hv = *reinterpret_cast<const ulonglong2*>(hbp + OFFW(i));
            r0 = ffma2(wR[i].x, hv.x, r0);
            r1 = ffma2(wR[i].y, hv.y, r1);
        }
        const float Rp = fold2(addf2(r0, r1));
        const float R = Rp + shx(Rp, 1);             // full rec dot on both parts
        // part0: rec tanh; part1: ic tanh. icx swaps them -> both compute same hn.
        const float inB = part ? fmaf(win, xv.x, bin) : (R + brec);
        const float tB = tanha(inB);
        const float icx = shx(tB, 1);
        const float hn = hprev + DT * ((icx + tB - hprev) * itau) * (1.0f + xv.y);
        if (!part) hs[half][hoff] = hn;
        hprev = hn;
        ewpq = xv.y;
        __syncthreads();
    }

    // ---- trailing acc update: tanh(W_acc @ h_S) with ew_{S-1} (part1 lanes)
    {
        ull a0 = 0, a1 = 0;
#pragma unroll
        for (int i = 0; i < 32; i++) {
            const ulonglong2 hv = *reinterpret_cast<const ulonglong2*>(hsb + OFFW(i));
            a0 = ffma2(wA[i].x, hv.x, a0);
            a1 = ffma2(wA[i].y, hv.y, a1);
        }
        const float dA = fold2(addf2(a0, a1));
        const float tA = tanha(dA + biasA);
        accq = 0.9f * accq + 0.1f * tA * ewpq;
    }

    // ---- epilogue: out[b] = (h_f + acc_f) . W_out + b_out
    const float accx = shx(accq, 1);      // part0 <- part1's acc state
    if (!part) hatts[half][hoff] = accx;  // hatts now holds acc_f; hs holds h_f
    __syncthreads();
    const int w = tid >> 5, l = tid & 31;
    if (w < NB) {
        float pacc = 0.0f;
#pragma unroll
        for (int i = 0; i < HH / 32; i++) {
            const int jo = i * PAD + l;
            pacc += (hs[w][jo] + hatts[w][jo]) * W_out[l + 32 * i];
        }
#pragma unroll
        for (int o = 16; o; o >>= 1) pacc += shx(pacc, o);
        if (l == 0) out[b0 + w] = pacc + b_out[0];
    }
}

extern "C" void kernel_launch(void* const* d_in, const int* in_sizes, int n_in,
                              void* d_out, int out_size) {
    const float* x     = (const float*)d_in[0];
    const float* W_in  = (const float*)d_in[1];
    const float* b_in  = (const float*)d_in[2];
    const float* W_rec = (const float*)d_in[3];
    const float* b_rec = (const float*)d_in[4];
    const float* tau   = (const float*)d_in[5];
    const float* W_att = (const float*)d_in[6];
    const float* b_att = (const float*)d_in[7];
    const float* W_ev  = (const float*)d_in[8];
    const float* b_ev  = (const float*)d_in[9];
    const float* W_acc = (const float*)d_in[10];
    const float* b_acc = (const float*)d_in[11];
    const float* W_out = (const float*)d_in[12];
    const float* b_out = (const float*)d_in[13];
    float* out = (float*)d_out;

    liquid_scan_kernel<<<BB / NB, NTHREADS>>>(x, W_in, b_in, W_rec, b_rec, tau,
                                              W_att, b_att, W_ev, b_ev,
                                              W_acc, b_acc, W_out, b_out, out);
}

// round 14
// speedup vs baseline: 3.6713x; 3.6713x over previous
#include <cuda_runtime.h>

// Problem shape (fixed by the dataset)
#define BB 256
#define SS 2048
#define HH 128
#define NB 2
#define NTHREADS 512
#define DT 0.1f
#define PAD 36           // floats per 32-float chunk (16B pad kills bank conflicts)
#define HPAD (4 * PAD)   // 144 floats per padded state vector

typedef unsigned long long ull;

// Packed fp32x2 FMA (Blackwell): two fp32 MACs per instruction.
__device__ __forceinline__ ull ffma2(ull a, ull b, ull c) {
    ull d;
    asm("fma.rn.f32x2 %0, %1, %2, %3;" : "=l"(d) : "l"(a), "l"(b), "l"(c));
    return d;
}
__device__ __forceinline__ float tanha(float x) {
    float t; asm("tanh.approx.f32 %0, %1;" : "=f"(t) : "f"(x)); return t;
}

// Reduce two packed row-partials (rows r0, r1 of this thread's group) across
// the 8-lane column group. Returns the full dot for THIS lane's row
// (row = 2g + bit2), replicated over the 4 q-lanes.
__device__ __forceinline__ float redq2(ull a0, ull a1, bool hiRow) {
    float l0, h0, l1, h1;
    asm("mov.b64 {%0, %1}, %2;" : "=f"(l0), "=f"(h0) : "l"(a0));
    asm("mov.b64 {%0, %1}, %2;" : "=f"(l1), "=f"(h1) : "l"(a1));
    const float s0 = l0 + h0;
    const float s1 = l1 + h1;
    // xor-4 exchange: low lanes keep row0 (send row1 partial), high lanes keep row1.
    const float x = hiRow ? s0 : s1;
    const float r = __shfl_xor_sync(0xffffffffu, x, 4);
    float s = (hiRow ? s1 : s0) + r;
    s += __shfl_xor_sync(0xffffffffu, s, 2);
    s += __shfl_xor_sync(0xffffffffu, s, 1);
    return s;
}

__global__ void __launch_bounds__(NTHREADS, 1)
liquid_scan_kernel(const float* __restrict__ x,
                   const float* __restrict__ W_in, const float* __restrict__ b_in,
                   const float* __restrict__ W_rec, const float* __restrict__ b_rec,
                   const float* __restrict__ tau,
                   const float* __restrict__ W_att, const float* __restrict__ b_att,
                   const float* __restrict__ W_ev, const float* __restrict__ b_ev,
                   const float* __restrict__ W_acc, const float* __restrict__ b_acc,
                   const float* __restrict__ W_out, const float* __restrict__ b_out,
                   float* __restrict__ out) {
    __shared__ __align__(16) float xs[NB][SS];       // input rows
    __shared__ __align__(16) float ews[NB][SS];      // event weights
    __shared__ __align__(16) float hs[NB][HPAD];     // hidden state (padded chunks)
    __shared__ __align__(16) float hatts[NB][HPAD];  // h * att (padded chunks)

    const int tid = threadIdx.x;
    const int g  = tid >> 3;      // row-pair group: rows 2g, 2g+1
    const int c  = tid & 7;       // 16-col block index within the row group
    const int h  = tid >> 2;      // row this lane owns after reduction (= 2g + bit2)
    const int q  = tid & 3;       // lane role
    const int p  = q & 1;         // batch parity for this lane's role
    const bool hiRow = (tid >> 2) & 1;
    const int b0 = blockIdx.x * NB;
    const int vbase = 16 * c + 4 * (c >> 1);          // padded float offset of col block
    const int hoff = (h >> 5) * PAD + (h & 31);       // padded scalar index for row h

    // ---- stage x rows into smem
    {
        const float4* xg0 = reinterpret_cast<const float4*>(x + (size_t)b0 * SS);
        const float4* xg1 = reinterpret_cast<const float4*>(x + (size_t)(b0 + 1) * SS);
        reinterpret_cast<float4*>(xs[0])[tid] = xg0[tid];
        reinterpret_cast<float4*>(xs[1])[tid] = xg1[tid];
    }
    if (tid < HPAD) { hs[0][tid] = 0.0f; hs[1][tid] = 0.0f; }
    __syncthreads();

    // ---- precompute event weights into smem AND the event_weights output
    {
        const float wev0 = W_ev[0], wev1 = W_ev[1], bev = b_ev[0];
        float* out_ew = out + BB;
#pragma unroll
        for (int k = 0; k < SS / NTHREADS; k++) {
            const int s = tid + k * NTHREADS;
#pragma unroll
            for (int b = 0; b < NB; b++) {
                float e = 0.0f;
                if (s > 0) {
                    float t = tanha(0.5f * (wev0 * xs[b][s] + wev1 * xs[b][s - 1] + bev));
                    e = fmaf(0.5f, t, 0.5f);
                }
                ews[b][s] = e;
                out_ew[(size_t)(b0 + b) * SS + s] = e;
            }
        }
    }

    // ---- weights into registers: 3 mats x 2 rows x 16 cols = 96 fp32
    ulonglong2 wa[2][4], wr[2][4], wc[2][4];
#pragma unroll
    for (int r = 0; r < 2; r++) {
        const int row = 2 * g + r;
        const ulonglong2* Wa = reinterpret_cast<const ulonglong2*>(W_att + row * HH + 16 * c);
        const ulonglong2* Wr = reinterpret_cast<const ulonglong2*>(W_rec + row * HH + 16 * c);
        const ulonglong2* Wc = reinterpret_cast<const ulonglong2*>(W_acc + row * HH + 16 * c);
#pragma unroll
        for (int k = 0; k < 4; k++) { wa[r][k] = Wa[k]; wr[r][k] = Wr[k]; wc[r][k] = Wc[k]; }
    }
    // Lane-role-folded scalars.
    const float pA_bias = (q < 2) ? b_att[h] : b_acc[h];   // phase A bias
    const float brec = b_rec[h];
    const float win  = W_in[h];
    const float bin  = b_in[h];
    const float itau = 1.0f / fminf(fmaxf(tau[h], 0.1f), 10.0f);

    float accq = 0.0f;   // acc state: q2 holds acc[batch0], q3 holds acc[batch1]
    float ewpq = 0.0f;   // previous step's event weight for this lane's batch

    __syncthreads();

#pragma unroll 1
    for (int s = 0; s < SS; s++) {
        // ---- phase A: att + acc matvecs on h_s, batch-sequential
        float A0, C0, A1, C1;
        {
            ull aa0 = 0, aa1 = 0, ac0 = 0, ac1 = 0;
#pragma unroll
            for (int k = 0; k < 4; k++) {
                const ulonglong2 hv = *reinterpret_cast<const ulonglong2*>(&hs[0][vbase + 4 * k]);
                aa0 = ffma2(wa[0][k].x, hv.x, aa0); aa0 = ffma2(wa[0][k].y, hv.y, aa0);
                aa1 = ffma2(wa[1][k].x, hv.x, aa1); aa1 = ffma2(wa[1][k].y, hv.y, aa1);
                ac0 = ffma2(wc[0][k].x, hv.x, ac0); ac0 = ffma2(wc[0][k].y, hv.y, ac0);
                ac1 = ffma2(wc[1][k].x, hv.x, ac1); ac1 = ffma2(wc[1][k].y, hv.y, ac1);
            }
            A0 = redq2(aa0, aa1, hiRow);
            C0 = redq2(ac0, ac1, hiRow);
        }
        {
            ull aa0 = 0, aa1 = 0, ac0 = 0, ac1 = 0;
#pragma unroll
            for (int k = 0; k < 4; k++) {
                const ulonglong2 hv = *reinterpret_cast<const ulonglong2*>(&hs[1][vbase + 4 * k]);
                aa0 = ffma2(wa[0][k].x, hv.x, aa0); aa0 = ffma2(wa[0][k].y, hv.y, aa0);
                aa1 = ffma2(wa[1][k].x, hv.x, aa1); aa1 = ffma2(wa[1][k].y, hv.y, aa1);
                ac0 = ffma2(wc[0][k].x, hv.x, ac0); ac0 = ffma2(wc[0][k].y, hv.y, ac0);
                ac1 = ffma2(wc[1][k].x, hv.x, ac1); ac1 = ffma2(wc[1][k].y, hv.y, ac1);
            }
            A1 = redq2(aa0, aa1, hiRow);
            C1 = redq2(ac0, ac1, hiRow);
        }

        // lane roles: q0->att(b0), q1->att(b1), q2->acc-tanh(b0), q3->acc-tanh(b1)
        const float inA = ((q & 2) ? (p ? C1 : C0) : (p ? A1 : A0)) + pA_bias;
        const float tA = tanha((q < 2) ? 0.5f * inA : inA);
        const float vA = (q < 2) ? fmaf(0.5f, tA, 0.5f) : tA;

        const float hold = hs[p][hoff];          // this lane's batch old h
        if (q < 2) {
            hatts[p][hoff] = hold * vA;          // q0 writes b0, q1 writes b1
        }
        accq = 0.9f * accq + 0.1f * vA * ewpq;   // meaningful on q2/q3 only
        __syncthreads();

        // ---- phase B: recurrence matvec on h*att, state update
        float R0, R1;
        {
            ull ar0 = 0, ar1 = 0;
#pragma unroll
            for (int k = 0; k < 4; k++) {
                const ulonglong2 hv = *reinterpret_cast<const ulonglong2*>(&hatts[0][vbase + 4 * k]);
                ar0 = ffma2(wr[0][k].x, hv.x, ar0); ar0 = ffma2(wr[0][k].y, hv.y, ar0);
                ar1 = ffma2(wr[1][k].x, hv.x, ar1); ar1 = ffma2(wr[1][k].y, hv.y, ar1);
            }
            R0 = redq2(ar0, ar1, hiRow);
        }
        {
            ull ar0 = 0, ar1 = 0;
#pragma unroll
            for (int k = 0; k < 4; k++) {
                const ulonglong2 hv = *reinterpret_cast<const ulonglong2*>(&hatts[1][vbase + 4 * k]);
                ar0 = ffma2(wr[0][k].x, hv.x, ar0); ar0 = ffma2(wr[0][k].y, hv.y, ar0);
                ar1 = ffma2(wr[1][k].x, hv.x, ar1); ar1 = ffma2(wr[1][k].y, hv.y, ar1);
            }
            R1 = redq2(ar0, ar1, hiRow);
        }

        const float xq = xs[p][s];
        const float ewq = ews[p][s];
        // lane roles: q0->rec(b0), q1->rec(b1), q2->ic(b0), q3->ic(b1)
        const float inB = (q & 2) ? fmaf(win, xq, bin) : ((p ? R1 : R0) + brec);
        const float tB = tanha(inB);
        const float icx = __shfl_xor_sync(0xffffffffu, tB, 2);  // q0<-ic0, q1<-ic1
        const float hn = hold + DT * ((icx + tB - hold) * itau) * (1.0f + ewq);
        if (q < 2) {
            hs[p][hoff] = hn;                    // q0 writes b0, q1 writes b1
        }
        ewpq = ewq;
        __syncthreads();
    }

    // ---- trailing acc update: tanh(W_acc @ h_S) with ew_{S-1}
    {
        ull c00 = 0, c01 = 0, c10 = 0, c11 = 0;
#pragma unroll
        for (int k = 0; k < 4; k++) {
            const ulonglong2 h0 = *reinterpret_cast<const ulonglong2*>(&hs[0][vbase + 4 * k]);
            const ulonglong2 h1 = *reinterpret_cast<const ulonglong2*>(&hs[1][vbase + 4 * k]);
            c00 = ffma2(wc[0][k].x, h0.x, c00); c00 = ffma2(wc[0][k].y, h0.y, c00);
            c01 = ffma2(wc[1][k].x, h0.x, c01); c01 = ffma2(wc[1][k].y, h0.y, c01);
            c10 = ffma2(wc[0][k].x, h1.x, c10); c10 = ffma2(wc[0][k].y, h1.y, c10);
            c11 = ffma2(wc[1][k].x, h1.x, c11); c11 = ffma2(wc[1][k].y, h1.y, c11);
        }
        const float C0 = redq2(c00, c01, hiRow);
        const float C1 = redq2(c10, c11, hiRow);
        const float t = tanha((p ? C1 : C0) + pA_bias);  // valid on q2/q3 (bias=bacc)
        accq = 0.9f * accq + 0.1f * t * ewpq;
    }

    // ---- epilogue: out[b] = (h_f + acc_f) . W_out + b_out
    if (q & 2) hatts[p][hoff] = accq;   // q2 -> acc[b0], q3 -> acc[b1]
    __syncthreads();
    const int w = tid >> 5, l = tid & 31;
    if (w < NB) {
        float pacc = 0.0f;
#pragma unroll
        for (int i = 0; i < HH / 32; i++) {
            const int jo = i * PAD + l;
            pacc += (hs[w][jo] + hatts[w][jo]) * W_out[l + 32 * i];
        }
#pragma unroll
        for (int o = 16; o; o >>= 1) pacc += __shfl_xor_sync(0xffffffffu, pacc, o);
        if (l == 0) out[b0 + w] = pacc + b_out[0];
    }
}

extern "C" void kernel_launch(void* const* d_in, const int* in_sizes, int n_in,
                              void* d_out, int out_size) {
    const float* x     = (const float*)d_in[0];
    const float* W_in  = (const float*)d_in[1];
    const float* b_in  = (const float*)d_in[2];
    const float* W_rec = (const float*)d_in[3];
    const float* b_rec = (const float*)d_in[4];
    const float* tau   = (const float*)d_in[5];
    const float* W_att = (const float*)d_in[6];
    const float* b_att = (const float*)d_in[7];
    const float* W_ev  = (const float*)d_in[8];
    const float* b_ev  = (const float*)d_in[9];
    const float* W_acc = (const float*)d_in[10];
    const float* b_acc = (const float*)d_in[11];
    const float* W_out = (const float*)d_in[12];
    const float* b_out = (const float*)d_in[13];
    float* out = (float*)d_out;

    liquid_scan_kernel<<<BB / NB, NTHREADS>>>(x, W_in, b_in, W_rec, b_rec, tau,
                                              W_att, b_att, W_ev, b_ev,
                                              W_acc, b_acc, W_out, b_out, out);
}